// round 14
// baseline (speedup 1.0000x reference)
#include <cuda_runtime.h>
#include <cuda_fp16.h>

#define N_NODES 100000
#define N_EDGES 1600000
#define C_IN    64
#define C_HID   64
#define C_OUT   32

#define SCAN_BLK 512
#define N_SCAN_BLOCKS ((N_NODES + SCAN_BLK - 1) / SCAN_BLK)   // 196

#define FIXP 16777216.0f   // 2^24 fixed-point scale for ew accumulation

#define GEMM1_BLOCKS ((N_NODES + 31) / 32)        // 3125 (32 rows/block)
#define FILL_BLOCKS  ((N_EDGES / 2 + 255) / 256)  // 3125
#define MERGED_BLOCKS (GEMM1_BLOCKS + FILL_BLOCKS) // 6250

// ----- scratch (device globals; zero-initialized at module load) ------------
__device__ unsigned long long g_pack[N_NODES];   // cnt<<40 | sum(ew)*2^24
__device__ float g_deg[N_NODES];                 // dinv
__device__ int   g_cnt[N_NODES];
__device__ int   g_rs [N_NODES];                 // CSR row start
__device__ int   g_rank[N_EDGES];                // edge rank within dst bucket

// decoupled-lookback scan state: (value<<2)|flag, flag: 0 none, 1 agg, 2 prefix
__device__ int                         g_tick;
__device__ volatile unsigned long long g_state[N_SCAN_BLOCKS];

struct EdgeRec { int src; float w; };            // w = ew (dinv folded into h)
__device__ EdgeRec g_csr[N_EDGES];

__device__ __align__(16) __half g_h1h[N_NODES * C_HID];  // dinv * (x @ W1)  fp16
__device__ __align__(16) float  g_o1 [N_NODES * C_HID];  // relu(layer-1 out)
__device__ __align__(16) __half g_h2h[N_NODES * C_OUT];  // dinv * (o1 @ W2) fp16

// NOTE: no k_init. g_pack/g_state/g_tick start zeroed (static init) and are
// re-zeroed at the end of every call by k_agg2, keeping each graph replay
// deterministic.

// one 64-bit atomic per edge; returned old count = rank within dst bucket.
__global__ void k_deg(const int* __restrict__ ei, const float* __restrict__ ew) {
    int t = blockIdx.x * blockDim.x + threadIdx.x;
    if (t < N_EDGES / 2) {
        int2   d2 = ((const int2*)(ei + N_EDGES))[t];
        float2 w2 = ((const float2*)ew)[t];
        unsigned long long o0 = atomicAdd(&g_pack[d2.x],
            (1ull << 40) | (unsigned long long)(w2.x * FIXP + 0.5f));
        unsigned long long o1 = atomicAdd(&g_pack[d2.y],
            (1ull << 40) | (unsigned long long)(w2.y * FIXP + 0.5f));
        ((int2*)g_rank)[t] = make_int2((int)(o0 >> 40), (int)(o1 >> 40));
    }
}

// single-pass scan (warp-parallel decoupled lookback): cnt, dinv, g_rs
__global__ void k_scan() {
    __shared__ int warp_sums[16];
    __shared__ int sh_bid, sh_exc;
    if (threadIdx.x == 0) sh_bid = atomicAdd(&g_tick, 1);
    __syncthreads();
    int bid = sh_bid;
    int i = bid * SCAN_BLK + threadIdx.x;

    int v = 0;
    if (i < N_NODES) {
        unsigned long long p = g_pack[i];
        v = (int)(p >> 40);
        g_cnt[i] = v;
        float deg = 1.0f + (float)(p & 0xFFFFFFFFFFull) * (1.0f / FIXP);
        g_deg[i] = rsqrtf(deg);
    }

    int lane = threadIdx.x & 31, wid = threadIdx.x >> 5;
    int inc = v;
    #pragma unroll
    for (int o = 1; o < 32; o <<= 1) {
        int t = __shfl_up_sync(0xffffffffu, inc, o);
        if (lane >= o) inc += t;
    }
    if (lane == 31) warp_sums[wid] = inc;
    __syncthreads();
    if (wid == 0) {
        int s = (lane < 16) ? warp_sums[lane] : 0;
        #pragma unroll
        for (int o = 1; o < 16; o <<= 1) {
            int t = __shfl_up_sync(0xffffffffu, s, o);
            if (lane >= o) s += t;
        }
        if (lane < 16) warp_sums[lane] = s;
    }
    __syncthreads();
    int incl = inc + ((wid > 0) ? warp_sums[wid - 1] : 0);
    int total = warp_sums[15];

    if (threadIdx.x == 0)
        g_state[bid] = ((unsigned long long)total << 2) | 1ull;

    if (wid == 0) {
        int exc = 0;
        if (bid > 0) {
            int j = bid - 1;
            while (true) {
                int jj = j - lane;
                unsigned long long s;
                do {
                    s = (jj >= 0) ? g_state[jj] : 2ull;   // jj<0: prefix of 0
                } while (__any_sync(0xffffffffu, (s & 3ull) == 0ull));
                unsigned pm = __ballot_sync(0xffffffffu, (s & 3ull) == 2ull);
                if (pm) {
                    int fp = __ffs(pm) - 1;               // nearest prefix
                    int val = (lane <= fp) ? (int)(s >> 2) : 0;
                    #pragma unroll
                    for (int o = 16; o; o >>= 1)
                        val += __shfl_xor_sync(0xffffffffu, val, o);
                    exc += val;
                    break;
                } else {
                    int val = (int)(s >> 2);
                    #pragma unroll
                    for (int o = 16; o; o >>= 1)
                        val += __shfl_xor_sync(0xffffffffu, val, o);
                    exc += val;
                    j -= 32;
                }
            }
        }
        if (lane == 0) {
            g_state[bid] = ((unsigned long long)(exc + total) << 2) | 2ull;
            sh_exc = exc;
        }
    }
    __syncthreads();
    if (i < N_NODES) g_rs[i] = sh_exc + incl - v;          // exclusive
}

// ---------------------------------------------------------------------------
// MERGED gemm1 + CSR fill. Lean smem (24KB) so fill blocks keep occupancy:
// 8 blocks/SM (thread-capped), 64 warps/SM vs 48 at R13's 35KB.
// Roles alternate 1:1 (even bid = gemm 32-row tile, odd bid = fill chunk).
//
// gemm1: h1h = dinv * (x @ W1), fp16 out. 2x4 thread tile, 32 rows x 64 ch.
// fill:  slot = rs[dst] + rank[e], 2 edges/thread, no atomics.
__global__ void k_gemm1_fill(const float* __restrict__ x,
                             const float* __restrict__ W1,
                             const int*   __restrict__ ei,
                             const float* __restrict__ ew) {
    __shared__ float ws[64][64];    // 16KB  [k][c], stride-64 (conflict-free here)
    __shared__ float xt[64][32];    // 8KB   [k][row]

    if (blockIdx.x & 1) {           // ---- CSR fill ----
        int t = (blockIdx.x >> 1) * 256 + threadIdx.x;
        if (t < N_EDGES / 2) {
            int2   s2 = ((const int2*)ei)[t];
            int2   d2 = ((const int2*)(ei + N_EDGES))[t];
            float2 w2 = ((const float2*)ew)[t];
            int2   r2 = ((const int2*)g_rank)[t];
            EdgeRec e0; e0.src = s2.x; e0.w = w2.x;
            g_csr[g_rs[d2.x] + r2.x] = e0;
            EdgeRec e1; e1.src = s2.y; e1.w = w2.y;
            g_csr[g_rs[d2.y] + r2.y] = e1;
        }
        return;
    }

    // ---- gemm1: 32 rows x 64 ch ----
    int gb = blockIdx.x >> 1;       // 0..GEMM1_BLOCKS-1
    int tid = threadIdx.x;
    int cg = tid & 15;              // channel group (4 ch)
    int rg = tid >> 4;              // row group (2 rows), 0..15
    int base = gb * 32;

    for (int i = tid; i < 64 * 16; i += 256) {
        int k = i >> 4, c4 = i & 15;
        *(float4*)&ws[k][c4 * 4] = ((const float4*)W1)[i];
    }
    for (int i = tid; i < 32 * 16; i += 256) {
        int r = i & 31, kc = i >> 5;
        float4 v = (base + r < N_NODES)
            ? ((const float4*)(x + (size_t)(base + r) * 64))[kc]
            : make_float4(0.f, 0.f, 0.f, 0.f);
        xt[4 * kc + 0][r] = v.x;
        xt[4 * kc + 1][r] = v.y;
        xt[4 * kc + 2][r] = v.z;
        xt[4 * kc + 3][r] = v.w;
    }
    __syncthreads();

    float acc[2][4];
    #pragma unroll
    for (int i = 0; i < 2; ++i)
        #pragma unroll
        for (int j = 0; j < 4; ++j) acc[i][j] = 0.f;

    #pragma unroll
    for (int k = 0; k < 64; ++k) {
        float2 xv = *(const float2*)&xt[k][rg * 2];
        float4 wv = *(const float4*)&ws[k][cg * 4];
        acc[0][0] += xv.x * wv.x; acc[0][1] += xv.x * wv.y;
        acc[0][2] += xv.x * wv.z; acc[0][3] += xv.x * wv.w;
        acc[1][0] += xv.y * wv.x; acc[1][1] += xv.y * wv.y;
        acc[1][2] += xv.y * wv.z; acc[1][3] += xv.y * wv.w;
    }

    #pragma unroll
    for (int i = 0; i < 2; ++i) {
        int row = base + rg * 2 + i;
        if (row < N_NODES) {
            float di = g_deg[row];
            __half2 h01 = __floats2half2_rn(di * acc[i][0], di * acc[i][1]);
            __half2 h23 = __floats2half2_rn(di * acc[i][2], di * acc[i][3]);
            __half2* dst = (__half2*)(g_h1h + (size_t)row * 64 + cg * 4);
            dst[0] = h01;
            dst[1] = h23;
        }
    }
}

// Aggregation layer 1: one warp per dst; unroll x8 for L2 MLP.
// (Launch index 3 this round -> directly measured by ncu.)
__global__ void k_agg1(const float* __restrict__ b1) {
    int w = (blockIdx.x * blockDim.x + threadIdx.x) >> 5;
    int lane = threadIdx.x & 31;
    if (w >= N_NODES) return;
    int beg = g_rs[w];
    int n   = g_cnt[w];
    const __half2* h1v = (const __half2*)g_h1h;

    float a0 = 0.f, a1 = 0.f;
    int i = 0;
    for (; i + 7 < n; i += 8) {
        EdgeRec e0 = g_csr[beg + i + 0];
        EdgeRec e1 = g_csr[beg + i + 1];
        EdgeRec e2 = g_csr[beg + i + 2];
        EdgeRec e3 = g_csr[beg + i + 3];
        EdgeRec e4 = g_csr[beg + i + 4];
        EdgeRec e5 = g_csr[beg + i + 5];
        EdgeRec e6 = g_csr[beg + i + 6];
        EdgeRec e7 = g_csr[beg + i + 7];
        float2 f0 = __half22float2(__ldg(h1v + (size_t)e0.src * 32 + lane));
        float2 f1 = __half22float2(__ldg(h1v + (size_t)e1.src * 32 + lane));
        float2 f2 = __half22float2(__ldg(h1v + (size_t)e2.src * 32 + lane));
        float2 f3 = __half22float2(__ldg(h1v + (size_t)e3.src * 32 + lane));
        float2 f4 = __half22float2(__ldg(h1v + (size_t)e4.src * 32 + lane));
        float2 f5 = __half22float2(__ldg(h1v + (size_t)e5.src * 32 + lane));
        float2 f6 = __half22float2(__ldg(h1v + (size_t)e6.src * 32 + lane));
        float2 f7 = __half22float2(__ldg(h1v + (size_t)e7.src * 32 + lane));
        a0 += e0.w * f0.x + e1.w * f1.x + e2.w * f2.x + e3.w * f3.x
            + e4.w * f4.x + e5.w * f5.x + e6.w * f6.x + e7.w * f7.x;
        a1 += e0.w * f0.y + e1.w * f1.y + e2.w * f2.y + e3.w * f3.y
            + e4.w * f4.y + e5.w * f5.y + e6.w * f6.y + e7.w * f7.y;
    }
    for (; i < n; ++i) {
        EdgeRec er = g_csr[beg + i];
        float2 f = __half22float2(__ldg(h1v + (size_t)er.src * 32 + lane));
        a0 += er.w * f.x;
        a1 += er.w * f.y;
    }
    float di = g_deg[w];
    float2 hs = __half22float2(h1v[(size_t)w * 32 + lane]);   // dinv-scaled
    float2 bb = ((const float2*)b1)[lane];
    a0 = di * a0 + di * hs.x + bb.x;
    a1 = di * a1 + di * hs.y + bb.y;
    ((float2*)g_o1)[(size_t)w * 32 + lane] =
        make_float2(fmaxf(a0, 0.f), fmaxf(a1, 0.f));
}

// GEMM2: h2h = dinv * (o1 @ W2), fp16 out. 4x4 outer-product register tile.
__global__ void k_gemm2(const float* __restrict__ W2) {
    __shared__ float ws2[64][36];   // [k][c]
    __shared__ float xt2[64][132];  // [k][row]
    int tid = threadIdx.x;
    int cg = tid & 7;               // channel group (4 ch)
    int rg = tid >> 3;              // row group (4 rows)
    int base = blockIdx.x * 128;

    for (int i = tid; i < 64 * 8; i += 256) {
        int k = i >> 3, c4 = i & 7;
        float4 v = ((const float4*)W2)[i];
        *(float4*)&ws2[k][c4 * 4] = v;
    }
    for (int i = tid; i < 128 * 16; i += 256) {
        int r = i & 127, kc = i >> 7;
        float4 v = (base + r < N_NODES)
            ? ((const float4*)(g_o1 + (size_t)(base + r) * 64))[kc]
            : make_float4(0.f, 0.f, 0.f, 0.f);
        xt2[4 * kc + 0][r] = v.x;
        xt2[4 * kc + 1][r] = v.y;
        xt2[4 * kc + 2][r] = v.z;
        xt2[4 * kc + 3][r] = v.w;
    }
    __syncthreads();

    float acc[4][4];
    #pragma unroll
    for (int i = 0; i < 4; ++i)
        #pragma unroll
        for (int j = 0; j < 4; ++j) acc[i][j] = 0.f;

    #pragma unroll
    for (int k = 0; k < 64; ++k) {
        float4 xv = *(const float4*)&xt2[k][rg * 4];
        float4 wv = *(const float4*)&ws2[k][cg * 4];
        acc[0][0] += xv.x * wv.x; acc[0][1] += xv.x * wv.y;
        acc[0][2] += xv.x * wv.z; acc[0][3] += xv.x * wv.w;
        acc[1][0] += xv.y * wv.x; acc[1][1] += xv.y * wv.y;
        acc[1][2] += xv.y * wv.z; acc[1][3] += xv.y * wv.w;
        acc[2][0] += xv.z * wv.x; acc[2][1] += xv.z * wv.y;
        acc[2][2] += xv.z * wv.z; acc[2][3] += xv.z * wv.w;
        acc[3][0] += xv.w * wv.x; acc[3][1] += xv.w * wv.y;
        acc[3][2] += xv.w * wv.z; acc[3][3] += xv.w * wv.w;
    }

    #pragma unroll
    for (int i = 0; i < 4; ++i) {
        int row = base + rg * 4 + i;
        if (row < N_NODES) {
            float di = g_deg[row];
            __half2 h01 = __floats2half2_rn(di * acc[i][0], di * acc[i][1]);
            __half2 h23 = __floats2half2_rn(di * acc[i][2], di * acc[i][3]);
            __half2* dst = (__half2*)(g_h2h + (size_t)row * 32 + cg * 4);
            dst[0] = h01;
            dst[1] = h23;
        }
    }
}

// Aggregation layer 2: warp per dst; half-warps interleave edges, unroll x4.
// Also resets prep state (g_pack/g_state/g_tick) for the next graph replay.
__global__ void k_agg2(const float* __restrict__ b2, float* __restrict__ out) {
    int gt = blockIdx.x * blockDim.x + threadIdx.x;

    // state reset for next call (g_pack/g_state no longer read this call)
    if (gt < N_NODES) g_pack[gt] = 0ull;
    if (gt < N_SCAN_BLOCKS) g_state[gt] = 0ull;
    if (gt == 0) g_tick = 0;

    int w = gt >> 5;
    int lane = threadIdx.x & 31;
    if (w >= N_NODES) return;
    int half = lane >> 4;      // 0 or 1
    int c2   = lane & 15;      // half2 index within node
    int beg = g_rs[w];
    int n   = g_cnt[w];
    const __half2* h2v = (const __half2*)g_h2h;

    float a0 = 0.f, a1 = 0.f;
    int i = half;
    for (; i + 6 < n; i += 8) {       // this half handles i, i+2, i+4, i+6
        EdgeRec ea = g_csr[beg + i];
        EdgeRec eb = g_csr[beg + i + 2];
        EdgeRec ec = g_csr[beg + i + 4];
        EdgeRec ed = g_csr[beg + i + 6];
        float2 fa = __half22float2(__ldg(h2v + (size_t)ea.src * 16 + c2));
        float2 fb = __half22float2(__ldg(h2v + (size_t)eb.src * 16 + c2));
        float2 fc = __half22float2(__ldg(h2v + (size_t)ec.src * 16 + c2));
        float2 fd = __half22float2(__ldg(h2v + (size_t)ed.src * 16 + c2));
        a0 += ea.w * fa.x + eb.w * fb.x + ec.w * fc.x + ed.w * fd.x;
        a1 += ea.w * fa.y + eb.w * fb.y + ec.w * fc.y + ed.w * fd.y;
    }
    for (; i < n; i += 2) {
        EdgeRec er = g_csr[beg + i];
        float2 f = __half22float2(__ldg(h2v + (size_t)er.src * 16 + c2));
        a0 += er.w * f.x;
        a1 += er.w * f.y;
    }
    a0 += __shfl_xor_sync(0xffffffffu, a0, 16);
    a1 += __shfl_xor_sync(0xffffffffu, a1, 16);

    if (half == 0) {
        float di = g_deg[w];
        float2 hs = __half22float2(h2v[(size_t)w * 16 + c2]);   // dinv-scaled
        float2 bb = ((const float2*)b2)[c2];
        float o0  = di * a0 + di * hs.x + bb.x;
        float o1v = di * a1 + di * hs.y + bb.y;
        ((float2*)out)[(size_t)w * 16 + c2] = make_float2(o0, o1v);
    }
}

// ---------------------------------------------------------------------------
extern "C" void kernel_launch(void* const* d_in, const int* in_sizes, int n_in,
                              void* d_out, int out_size) {
    const float* x  = (const float*)d_in[0];
    const int*   ei = (const int*)d_in[1];
    const float* ew = (const float*)d_in[2];
    const float* W1 = (const float*)d_in[3];
    const float* b1 = (const float*)d_in[4];
    const float* W2 = (const float*)d_in[5];
    const float* b2 = (const float*)d_in[6];
    float* out = (float*)d_out;

    k_deg  <<<(N_EDGES / 2 + 255) / 256, 256>>>(ei, ew);    // idx 0
    k_scan <<<N_SCAN_BLOCKS, SCAN_BLK>>>();                 // idx 1
    k_gemm1_fill<<<MERGED_BLOCKS, 256>>>(x, W1, ei, ew);    // idx 2
    k_agg1 <<<(N_NODES * 32 + 255) / 256, 256>>>(b1);       // idx 3 (ncu)
    k_gemm2<<<(N_NODES + 127) / 128, 256>>>(W2);            // idx 4
    k_agg2 <<<(N_NODES * 32 + 255) / 256, 256>>>(b2, out);  // idx 5
}

// round 15
// speedup vs baseline: 1.0569x; 1.0569x over previous
#include <cuda_runtime.h>
#include <cuda_fp16.h>

#define N_NODES 100000
#define N_EDGES 1600000
#define C_IN    64
#define C_HID   64
#define C_OUT   32

#define SCAN_BLK 512
#define N_SCAN_BLOCKS ((N_NODES + SCAN_BLK - 1) / SCAN_BLK)   // 196

#define FIXP 16777216.0f   // 2^24 fixed-point scale for ew accumulation

#define GEMM1_BLOCKS ((N_NODES + 63) / 64)        // 1563
#define FILL_BLOCKS  ((N_EDGES / 2 + 255) / 256)  // 3125
#define MERGED_BLOCKS (GEMM1_BLOCKS + FILL_BLOCKS) // 4688

// ----- scratch (device globals; zero-initialized at module load) ------------
__device__ unsigned long long g_pack[N_NODES];   // cnt<<40 | sum(ew)*2^24
__device__ float g_deg[N_NODES];                 // dinv
__device__ int   g_cnt[N_NODES];                 // real in-degree
__device__ int   g_rs [N_NODES];                 // CSR row start (16B-aligned)
__device__ int   g_rank[N_EDGES];                // edge rank within dst bucket

// decoupled-lookback scan state: (value<<2)|flag, flag: 0 none, 1 agg, 2 prefix
__device__ int                         g_tick;
__device__ volatile unsigned long long g_state[N_SCAN_BLOCKS];

struct EdgeRec { int src; float w; };            // w = ew (dinv folded into h)
// padded: each bucket start rounded to even index (16B) -> +<=1 slot per node
__device__ __align__(16) EdgeRec g_csr[N_EDGES + N_NODES];

__device__ __align__(16) __half g_h1h[N_NODES * C_HID];  // dinv * (x @ W1)  fp16
__device__ __align__(16) float  g_o1 [N_NODES * C_HID];  // relu(layer-1 out)
__device__ __align__(16) __half g_h2h[N_NODES * C_OUT];  // dinv * (o1 @ W2) fp16

// NOTE: no k_init. g_pack/g_state/g_tick start zeroed (static init) and are
// re-zeroed at the end of every call by k_agg2 (deterministic graph replays).

// one 64-bit atomic per edge; returned old count = rank within dst bucket.
__global__ void k_deg(const int* __restrict__ ei, const float* __restrict__ ew) {
    int t = blockIdx.x * blockDim.x + threadIdx.x;
    if (t < N_EDGES / 2) {
        int2   d2 = ((const int2*)(ei + N_EDGES))[t];
        float2 w2 = ((const float2*)ew)[t];
        unsigned long long o0 = atomicAdd(&g_pack[d2.x],
            (1ull << 40) | (unsigned long long)(w2.x * FIXP + 0.5f));
        unsigned long long o1 = atomicAdd(&g_pack[d2.y],
            (1ull << 40) | (unsigned long long)(w2.y * FIXP + 0.5f));
        ((int2*)g_rank)[t] = make_int2((int)(o0 >> 40), (int)(o1 >> 40));
    }
}

// single-pass scan (warp-parallel decoupled lookback). Scans PADDED counts
// (cnt rounded up to even) so every bucket start is 16B-aligned in g_csr.
__global__ void k_scan() {
    __shared__ int warp_sums[16];
    __shared__ int sh_bid, sh_exc;
    if (threadIdx.x == 0) sh_bid = atomicAdd(&g_tick, 1);
    __syncthreads();
    int bid = sh_bid;
    int i = bid * SCAN_BLK + threadIdx.x;

    int v = 0, pc = 0;
    if (i < N_NODES) {
        unsigned long long p = g_pack[i];
        v = (int)(p >> 40);
        pc = v + (v & 1);                 // pad to even
        g_cnt[i] = v;
        float deg = 1.0f + (float)(p & 0xFFFFFFFFFFull) * (1.0f / FIXP);
        g_deg[i] = rsqrtf(deg);
    }

    int lane = threadIdx.x & 31, wid = threadIdx.x >> 5;
    int inc = pc;
    #pragma unroll
    for (int o = 1; o < 32; o <<= 1) {
        int t = __shfl_up_sync(0xffffffffu, inc, o);
        if (lane >= o) inc += t;
    }
    if (lane == 31) warp_sums[wid] = inc;
    __syncthreads();
    if (wid == 0) {
        int s = (lane < 16) ? warp_sums[lane] : 0;
        #pragma unroll
        for (int o = 1; o < 16; o <<= 1) {
            int t = __shfl_up_sync(0xffffffffu, s, o);
            if (lane >= o) s += t;
        }
        if (lane < 16) warp_sums[lane] = s;
    }
    __syncthreads();
    int incl = inc + ((wid > 0) ? warp_sums[wid - 1] : 0);
    int total = warp_sums[15];

    if (threadIdx.x == 0)
        g_state[bid] = ((unsigned long long)total << 2) | 1ull;

    if (wid == 0) {
        int exc = 0;
        if (bid > 0) {
            int j = bid - 1;
            while (true) {
                int jj = j - lane;
                unsigned long long s;
                do {
                    s = (jj >= 0) ? g_state[jj] : 2ull;   // jj<0: prefix of 0
                } while (__any_sync(0xffffffffu, (s & 3ull) == 0ull));
                unsigned pm = __ballot_sync(0xffffffffu, (s & 3ull) == 2ull);
                if (pm) {
                    int fp = __ffs(pm) - 1;               // nearest prefix
                    int val = (lane <= fp) ? (int)(s >> 2) : 0;
                    #pragma unroll
                    for (int o = 16; o; o >>= 1)
                        val += __shfl_xor_sync(0xffffffffu, val, o);
                    exc += val;
                    break;
                } else {
                    int val = (int)(s >> 2);
                    #pragma unroll
                    for (int o = 16; o; o >>= 1)
                        val += __shfl_xor_sync(0xffffffffu, val, o);
                    exc += val;
                    j -= 32;
                }
            }
        }
        if (lane == 0) {
            g_state[bid] = ((unsigned long long)(exc + total) << 2) | 2ull;
            sh_exc = exc;
        }
    }
    __syncthreads();
    if (i < N_NODES) g_rs[i] = sh_exc + incl - pc;         // exclusive, even
}

// ---------------------------------------------------------------------------
// MERGED gemm1 + CSR fill (R13 champion structure: 4x4 tile, 1:2 interleave).
__global__ void k_gemm1_fill(const float* __restrict__ x,
                             const float* __restrict__ W1,
                             const int*   __restrict__ ei,
                             const float* __restrict__ ew) {
    __shared__ float ws[64][68];    // [k][c]
    __shared__ float xt[64][68];    // [k][row]

    if (blockIdx.x % 3 != 0) {      // ---- CSR fill ----
        int fb = blockIdx.x - blockIdx.x / 3 - 1;   // 0..FILL_BLOCKS-1
        int t = fb * 256 + threadIdx.x;
        if (t < N_EDGES / 2) {
            int2   s2 = ((const int2*)ei)[t];
            int2   d2 = ((const int2*)(ei + N_EDGES))[t];
            float2 w2 = ((const float2*)ew)[t];
            int2   r2 = ((const int2*)g_rank)[t];
            EdgeRec e0; e0.src = s2.x; e0.w = w2.x;
            g_csr[g_rs[d2.x] + r2.x] = e0;
            EdgeRec e1; e1.src = s2.y; e1.w = w2.y;
            g_csr[g_rs[d2.y] + r2.y] = e1;
        }
        return;
    }

    // ---- gemm1: 64 rows x 64 ch, 4x4 outer-product tile ----
    int gb = blockIdx.x / 3;
    int tid = threadIdx.x;
    int cg = tid & 15;              // channel group (4 ch)
    int rg = tid >> 4;              // row group (4 rows)
    int base = gb * 64;

    for (int i = tid; i < 64 * 16; i += 256) {
        int k = i >> 4, c4 = i & 15;
        float4 v = ((const float4*)W1)[i];
        *(float4*)&ws[k][c4 * 4] = v;
    }
    for (int i = tid; i < 64 * 16; i += 256) {
        int r = i & 63, kc = i >> 6;
        float4 v = (base + r < N_NODES)
            ? ((const float4*)(x + (size_t)(base + r) * 64))[kc]
            : make_float4(0.f, 0.f, 0.f, 0.f);
        xt[4 * kc + 0][r] = v.x;
        xt[4 * kc + 1][r] = v.y;
        xt[4 * kc + 2][r] = v.z;
        xt[4 * kc + 3][r] = v.w;
    }
    __syncthreads();

    float acc[4][4];
    #pragma unroll
    for (int i = 0; i < 4; ++i)
        #pragma unroll
        for (int j = 0; j < 4; ++j) acc[i][j] = 0.f;

    #pragma unroll
    for (int k = 0; k < 64; ++k) {
        float4 xv = *(const float4*)&xt[k][rg * 4];
        float4 wv = *(const float4*)&ws[k][cg * 4];
        acc[0][0] += xv.x * wv.x; acc[0][1] += xv.x * wv.y;
        acc[0][2] += xv.x * wv.z; acc[0][3] += xv.x * wv.w;
        acc[1][0] += xv.y * wv.x; acc[1][1] += xv.y * wv.y;
        acc[1][2] += xv.y * wv.z; acc[1][3] += xv.y * wv.w;
        acc[2][0] += xv.z * wv.x; acc[2][1] += xv.z * wv.y;
        acc[2][2] += xv.z * wv.z; acc[2][3] += xv.z * wv.w;
        acc[3][0] += xv.w * wv.x; acc[3][1] += xv.w * wv.y;
        acc[3][2] += xv.w * wv.z; acc[3][3] += xv.w * wv.w;
    }

    #pragma unroll
    for (int i = 0; i < 4; ++i) {
        int row = base + rg * 4 + i;
        if (row < N_NODES) {
            float di = g_deg[row];
            __half2 h01 = __floats2half2_rn(di * acc[i][0], di * acc[i][1]);
            __half2 h23 = __floats2half2_rn(di * acc[i][2], di * acc[i][3]);
            __half2* dst = (__half2*)(g_h1h + (size_t)row * 64 + cg * 4);
            dst[0] = h01;
            dst[1] = h23;
        }
    }
}

// Aggregation layer 1: one warp per dst. EdgeRecs loaded TWO per LDG.128
// (bucket starts 16B-aligned) -> 1.5 LDG/edge instead of 2. Unroll 4 pairs.
__global__ void k_agg1(const float* __restrict__ b1) {
    int w = (blockIdx.x * blockDim.x + threadIdx.x) >> 5;
    int lane = threadIdx.x & 31;
    if (w >= N_NODES) return;
    int beg = g_rs[w];                       // even
    int n   = g_cnt[w];
    const __half2* h1v = (const __half2*)g_h1h;
    const int4* cp = (const int4*)(g_csr + beg);   // 16B-aligned

    float a0 = 0.f, a1 = 0.f;
    int npair = n >> 1;
    int j = 0;
    for (; j + 3 < npair; j += 4) {          // 8 edges
        int4 q0 = __ldg(cp + j + 0);
        int4 q1 = __ldg(cp + j + 1);
        int4 q2 = __ldg(cp + j + 2);
        int4 q3 = __ldg(cp + j + 3);
        float2 f0 = __half22float2(__ldg(h1v + (size_t)q0.x * 32 + lane));
        float2 f1 = __half22float2(__ldg(h1v + (size_t)q0.z * 32 + lane));
        float2 f2 = __half22float2(__ldg(h1v + (size_t)q1.x * 32 + lane));
        float2 f3 = __half22float2(__ldg(h1v + (size_t)q1.z * 32 + lane));
        float2 f4 = __half22float2(__ldg(h1v + (size_t)q2.x * 32 + lane));
        float2 f5 = __half22float2(__ldg(h1v + (size_t)q2.z * 32 + lane));
        float2 f6 = __half22float2(__ldg(h1v + (size_t)q3.x * 32 + lane));
        float2 f7 = __half22float2(__ldg(h1v + (size_t)q3.z * 32 + lane));
        float w0 = __int_as_float(q0.y), w1 = __int_as_float(q0.w);
        float w2 = __int_as_float(q1.y), w3 = __int_as_float(q1.w);
        float w4 = __int_as_float(q2.y), w5 = __int_as_float(q2.w);
        float w6 = __int_as_float(q3.y), w7 = __int_as_float(q3.w);
        a0 += w0 * f0.x + w1 * f1.x + w2 * f2.x + w3 * f3.x
            + w4 * f4.x + w5 * f5.x + w6 * f6.x + w7 * f7.x;
        a1 += w0 * f0.y + w1 * f1.y + w2 * f2.y + w3 * f3.y
            + w4 * f4.y + w5 * f5.y + w6 * f6.y + w7 * f7.y;
    }
    for (; j < npair; ++j) {                 // 2 edges
        int4 q = __ldg(cp + j);
        float2 fa = __half22float2(__ldg(h1v + (size_t)q.x * 32 + lane));
        float2 fb = __half22float2(__ldg(h1v + (size_t)q.z * 32 + lane));
        float wa = __int_as_float(q.y), wb = __int_as_float(q.w);
        a0 += wa * fa.x + wb * fb.x;
        a1 += wa * fa.y + wb * fb.y;
    }
    if (n & 1) {                             // odd tail edge
        EdgeRec er = g_csr[beg + n - 1];
        float2 f = __half22float2(__ldg(h1v + (size_t)er.src * 32 + lane));
        a0 += er.w * f.x;
        a1 += er.w * f.y;
    }
    float di = g_deg[w];
    float2 hs = __half22float2(h1v[(size_t)w * 32 + lane]);   // dinv-scaled
    float2 bb = ((const float2*)b1)[lane];
    a0 = di * a0 + di * hs.x + bb.x;
    a1 = di * a1 + di * hs.y + bb.y;
    ((float2*)g_o1)[(size_t)w * 32 + lane] =
        make_float2(fmaxf(a0, 0.f), fmaxf(a1, 0.f));
}

// GEMM2: h2h = dinv * (o1 @ W2), fp16 out. 4x4 outer-product register tile.
__global__ void k_gemm2(const float* __restrict__ W2) {
    __shared__ float ws2[64][36];   // [k][c]
    __shared__ float xt2[64][132];  // [k][row]
    int tid = threadIdx.x;
    int cg = tid & 7;               // channel group (4 ch)
    int rg = tid >> 3;              // row group (4 rows)
    int base = blockIdx.x * 128;

    for (int i = tid; i < 64 * 8; i += 256) {
        int k = i >> 3, c4 = i & 7;
        float4 v = ((const float4*)W2)[i];
        *(float4*)&ws2[k][c4 * 4] = v;
    }
    for (int i = tid; i < 128 * 16; i += 256) {
        int r = i & 127, kc = i >> 7;
        float4 v = (base + r < N_NODES)
            ? ((const float4*)(g_o1 + (size_t)(base + r) * 64))[kc]
            : make_float4(0.f, 0.f, 0.f, 0.f);
        xt2[4 * kc + 0][r] = v.x;
        xt2[4 * kc + 1][r] = v.y;
        xt2[4 * kc + 2][r] = v.z;
        xt2[4 * kc + 3][r] = v.w;
    }
    __syncthreads();

    float acc[4][4];
    #pragma unroll
    for (int i = 0; i < 4; ++i)
        #pragma unroll
        for (int j = 0; j < 4; ++j) acc[i][j] = 0.f;

    #pragma unroll
    for (int k = 0; k < 64; ++k) {
        float4 xv = *(const float4*)&xt2[k][rg * 4];
        float4 wv = *(const float4*)&ws2[k][cg * 4];
        acc[0][0] += xv.x * wv.x; acc[0][1] += xv.x * wv.y;
        acc[0][2] += xv.x * wv.z; acc[0][3] += xv.x * wv.w;
        acc[1][0] += xv.y * wv.x; acc[1][1] += xv.y * wv.y;
        acc[1][2] += xv.y * wv.z; acc[1][3] += xv.y * wv.w;
        acc[2][0] += xv.z * wv.x; acc[2][1] += xv.z * wv.y;
        acc[2][2] += xv.z * wv.z; acc[2][3] += xv.z * wv.w;
        acc[3][0] += xv.w * wv.x; acc[3][1] += xv.w * wv.y;
        acc[3][2] += xv.w * wv.z; acc[3][3] += xv.w * wv.w;
    }

    #pragma unroll
    for (int i = 0; i < 4; ++i) {
        int row = base + rg * 4 + i;
        if (row < N_NODES) {
            float di = g_deg[row];
            __half2 h01 = __floats2half2_rn(di * acc[i][0], di * acc[i][1]);
            __half2 h23 = __floats2half2_rn(di * acc[i][2], di * acc[i][3]);
            __half2* dst = (__half2*)(g_h2h + (size_t)row * 32 + cg * 4);
            dst[0] = h01;
            dst[1] = h23;
        }
    }
}

// Aggregation layer 2: warp per dst; half-warps interleave edges, unroll x4.
// Also resets prep state (g_pack/g_state/g_tick) for the next graph replay.
__global__ void k_agg2(const float* __restrict__ b2, float* __restrict__ out) {
    int gt = blockIdx.x * blockDim.x + threadIdx.x;

    // state reset for next call (these arrays are no longer read this call)
    if (gt < N_NODES) g_pack[gt] = 0ull;
    if (gt < N_SCAN_BLOCKS) g_state[gt] = 0ull;
    if (gt == 0) g_tick = 0;

    int w = gt >> 5;
    int lane = threadIdx.x & 31;
    if (w >= N_NODES) return;
    int half = lane >> 4;      // 0 or 1
    int c2   = lane & 15;      // half2 index within node
    int beg = g_rs[w];
    int n   = g_cnt[w];
    const __half2* h2v = (const __half2*)g_h2h;

    float a0 = 0.f, a1 = 0.f;
    int i = half;
    for (; i + 6 < n; i += 8) {       // this half handles i, i+2, i+4, i+6
        EdgeRec ea = g_csr[beg + i];
        EdgeRec eb = g_csr[beg + i + 2];
        EdgeRec ec = g_csr[beg + i + 4];
        EdgeRec ed = g_csr[beg + i + 6];
        float2 fa = __half22float2(__ldg(h2v + (size_t)ea.src * 16 + c2));
        float2 fb = __half22float2(__ldg(h2v + (size_t)eb.src * 16 + c2));
        float2 fc = __half22float2(__ldg(h2v + (size_t)ec.src * 16 + c2));
        float2 fd = __half22float2(__ldg(h2v + (size_t)ed.src * 16 + c2));
        a0 += ea.w * fa.x + eb.w * fb.x + ec.w * fc.x + ed.w * fd.x;
        a1 += ea.w * fa.y + eb.w * fb.y + ec.w * fc.y + ed.w * fd.y;
    }
    for (; i < n; i += 2) {
        EdgeRec er = g_csr[beg + i];
        float2 f = __half22float2(__ldg(h2v + (size_t)er.src * 16 + c2));
        a0 += er.w * f.x;
        a1 += er.w * f.y;
    }
    a0 += __shfl_xor_sync(0xffffffffu, a0, 16);
    a1 += __shfl_xor_sync(0xffffffffu, a1, 16);

    if (half == 0) {
        float di = g_deg[w];
        float2 hs = __half22float2(h2v[(size_t)w * 16 + c2]);   // dinv-scaled
        float2 bb = ((const float2*)b2)[c2];
        float o0  = di * a0 + di * hs.x + bb.x;
        float o1v = di * a1 + di * hs.y + bb.y;
        ((float2*)out)[(size_t)w * 16 + c2] = make_float2(o0, o1v);
    }
}

// ---------------------------------------------------------------------------
extern "C" void kernel_launch(void* const* d_in, const int* in_sizes, int n_in,
                              void* d_out, int out_size) {
    const float* x  = (const float*)d_in[0];
    const int*   ei = (const int*)d_in[1];
    const float* ew = (const float*)d_in[2];
    const float* W1 = (const float*)d_in[3];
    const float* b1 = (const float*)d_in[4];
    const float* W2 = (const float*)d_in[5];
    const float* b2 = (const float*)d_in[6];
    float* out = (float*)d_out;

    k_deg  <<<(N_EDGES / 2 + 255) / 256, 256>>>(ei, ew);    // idx 0
    k_scan <<<N_SCAN_BLOCKS, SCAN_BLK>>>();                 // idx 1
    k_gemm1_fill<<<MERGED_BLOCKS, 256>>>(x, W1, ei, ew);    // idx 2
    k_agg1 <<<(N_NODES * 32 + 255) / 256, 256>>>(b1);       // idx 3 (ncu)
    k_gemm2<<<(N_NODES + 127) / 128, 256>>>(W2);            // idx 4
    k_agg2 <<<(N_NODES * 32 + 255) / 256, 256>>>(b2, out);  // idx 5
}